// round 16
// baseline (speedup 1.0000x reference)
#include <cuda_runtime.h>
#include <cuda_bf16.h>

#define Bsz   128
#define Tlen  80
#define Edim  100
#define Udim  512

// 8 groups (16 rows) x 16 col-slice CTAs; each group = one 16-CTA cluster.
#define NCTA  128
#define NTHR  256
#define GSZ   16
#define NGRP  8
#define RPC   16
#define PADK  516
#define APAD  72
#define BPAD  40

#define OFF_WA 0                          // 64 cols x PADK
#define OFF_WB (64 * PADK)                // 32 cols x PADK
#define OFF_H  (96 * PADK)                // 16 rows x PADK (strip area)
#define OFF_RED OFF_H                     // RED overlaps H (H dead post-FMA)
#define OFF_MB  (OFF_H + RPC * PADK)      // 2 mbarriers (16B) + pad
#define SMEM_FLOATS (OFF_MB + 32)
#define SMEM_BYTES  (SMEM_FLOATS * 4)     // 231296 B <= 232448

typedef unsigned long long u64;

__device__ float g_P0[Tlen * Bsz * Udim];
__device__ float g_h [Bsz * Udim];
__device__ float g_h0[Bsz * Udim];
__device__ float g_r1[Bsz * Udim];

// ---------------- helpers ----------------

__device__ __forceinline__ u64 ffma2(u64 a, u64 b, u64 c) {
    u64 d;
    asm("fma.rn.f32x2 %0, %1, %2, %3;" : "=l"(d) : "l"(a), "l"(b), "l"(c));
    return d;
}
__device__ __forceinline__ float fsum(u64 v) {
    float lo, hi;
    asm("mov.b64 {%0, %1}, %2;" : "=f"(lo), "=f"(hi) : "l"(v));
    return lo + hi;
}
__device__ __forceinline__ float tanh_fast(float x) {
    float e = __expf(2.0f * x);
    return 1.0f - __fdividef(2.0f, e + 1.0f);
}
__device__ __forceinline__ unsigned smem_u32(const void* p) {
    unsigned a;
    asm("{ .reg .u64 t; cvta.to.shared.u64 t, %1; cvt.u32.u64 %0, t; }"
        : "=r"(a) : "l"(p));
    return a;
}
__device__ __forceinline__ void mbar_init(unsigned a, unsigned cnt) {
    asm volatile("mbarrier.init.shared.b64 [%0], %1;" :: "r"(a), "r"(cnt) : "memory");
}
// Remote arrive on cluster rank's copy of this barrier (release, cluster scope).
__device__ __forceinline__ void mbar_arrive_rank(unsigned a, unsigned rank) {
    asm volatile(
        "{ .reg .b32 r;\n\t"
        "mapa.shared::cluster.u32 r, %0, %1;\n\t"
        "mbarrier.arrive.release.cluster.shared::cluster.b64 _, [r]; }"
        :: "r"(a), "r"(rank) : "memory");
}
// Local wait (acquire, cluster scope) with HW-sleep try_wait.
__device__ __forceinline__ void mbar_wait(unsigned a, unsigned parity) {
    asm volatile(
        "{ .reg .pred P;\n\t"
        "WL%=:\n\t"
        "mbarrier.try_wait.parity.acquire.cluster.shared::cta.b64 P, [%0], %1, 0x989680;\n\t"
        "@P bra WD%=;\n\t"
        "bra WL%=;\n\t"
        "WD%=: }"
        :: "r"(a), "r"(parity) : "memory");
}
__device__ __forceinline__ void cluster_sync() {
    asm volatile("barrier.cluster.arrive.aligned;" ::: "memory");
    asm volatile("barrier.cluster.wait.aligned;" ::: "memory");
}

// Warp loads its own 8-row x 128-col window (coalesced LDG.128, clean STS).
__device__ __forceinline__ void load_strip(float* HTw, const float* src) {
    const int lane = threadIdx.x & 31;
    float4 v[8];
#pragma unroll
    for (int r = 0; r < 8; r++)
        v[r] = __ldcg((const float4*)(src + r * Udim) + lane);
#pragma unroll
    for (int r = 0; r < 8; r++)
        *(float4*)(HTw + r * PADK + lane * 4) = v[r];
    __syncwarp();
}

// ---------------- kernel 1: P0 = emb[tokens] @ k0 + b0 ----------------

#define PC_PAIRS 16
#define PTHR 128

__global__ void __launch_bounds__(PTHR) pre_kernel(
    const int* __restrict__ tokens, const float* __restrict__ emb,
    const float* __restrict__ k0, const float* __restrict__ b0)
{
    __shared__ int    tok[PC_PAIRS];
    __shared__ float2 xs2[PC_PAIRS][Edim];

    const int tid = threadIdx.x;

    if (blockIdx.x < 64) {
        int base = blockIdx.x * 1024 + tid * 8;
        float4 z = make_float4(0.f, 0.f, 0.f, 0.f);
        *(float4*)(g_h + base)     = z;
        *(float4*)(g_h + base + 4) = z;
    }

    const int pbase = blockIdx.x * PC_PAIRS;
    if (tid < PC_PAIRS) tok[tid] = tokens[pbase + tid];
    __syncthreads();

    for (int e = tid; e < PC_PAIRS * Edim; e += PTHR) {
        int p = e / Edim, k = e - p * Edim;
        float v = emb[tok[p] * Edim + k];
        xs2[p][k] = make_float2(v, v);
    }
    __syncthreads();

    const int u = tid * 4;
    u64 acc[PC_PAIRS][2];
#pragma unroll
    for (int p = 0; p < PC_PAIRS; p++) { acc[p][0] = 0ull; acc[p][1] = 0ull; }

    for (int k = 0; k < Edim; k++) {
        ulonglong2 wv = *(const ulonglong2*)(k0 + k * Udim + u);
#pragma unroll
        for (int p = 0; p < PC_PAIRS; p++) {
            u64 x2 = *(const u64*)&xs2[p][k];
            acc[p][0] = ffma2(x2, wv.x, acc[p][0]);
            acc[p][1] = ffma2(x2, wv.y, acc[p][1]);
        }
    }

    float4 bv = *(const float4*)(b0 + u);
#pragma unroll
    for (int p = 0; p < PC_PAIRS; p++) {
        int pi = pbase + p;
        int b = pi / Tlen;
        int t = pi - b * Tlen;
        float2 lo, hi;
        asm("mov.b64 {%0, %1}, %2;" : "=f"(lo.x), "=f"(lo.y) : "l"(acc[p][0]));
        asm("mov.b64 {%0, %1}, %2;" : "=f"(hi.x), "=f"(hi.y) : "l"(acc[p][1]));
        float4 o = make_float4(lo.x + bv.x, lo.y + bv.y, hi.x + bv.z, hi.y + bv.w);
        *(float4*)(g_P0 + ((size_t)(t * Bsz) + b) * Udim + u) = o;
    }
}

// ---------------- kernel 2: persistent scan, cluster-synced ----------------

__global__ void __launch_bounds__(NTHR, 1) __cluster_dims__(GSZ, 1, 1)
rnn_kernel(
    const float* __restrict__ rk0, const float* __restrict__ rk1,
    const float* __restrict__ k1,  const float* __restrict__ b1,
    const float* __restrict__ wd,  const float* __restrict__ bd,
    float* __restrict__ out)
{
    extern __shared__ float sm[];
    const int tid  = threadIdx.x;
    const int g    = blockIdx.x >> 4;
    const int j    = blockIdx.x & 15;     // == cluster rank
    const int r0   = g * RPC;
    const int w    = tid >> 5;
    const int lane = tid & 31;
    const int q    = w & 3;
    const int hh   = w >> 2;
    const bool isA0 = (j < 8);

    const unsigned smb   = smem_u32(sm);
    const unsigned mbarA = smb + OFF_MB * 4;
    const unsigned mbarB = mbarA + 8;

    if (tid == 0) { mbar_init(mbarA, GSZ); mbar_init(mbarB, GSZ); }

    // weights into SMEM (once), transposed [col][K]
    const float* wsrcA = isA0 ? rk0 : rk1;
    const int cbaseA = (j & 7) * 64;
    for (int e = tid; e < 64 * Udim; e += NTHR) {
        int k = e >> 6, cc = e & 63;
        sm[OFF_WA + cc * PADK + k] = wsrcA[k * Udim + cbaseA + cc];
    }
    const int cbaseB = j * 32;
    for (int e = tid; e < 32 * Udim; e += NTHR) {
        int k = e >> 5, cc = e & 31;
        sm[OFF_WB + cc * PADK + k] = k1[k * Udim + cbaseB + cc];
    }

    const int rg = lane & 3;
    const int cg = lane >> 2;
    const int frow = tid >> 4;
    const int fcA  = (tid & 15) * 4;
    const int fcB  = (tid & 15) * 2;

    float4 b1v = make_float4(0.f, 0.f, 0.f, 0.f);
    if (!isA0) b1v = *(const float4*)(b1 + cbaseA + fcA);
    __syncthreads();
    cluster_sync();           // peers' mbarriers initialized before any arrive

    const float* Hp  = sm + OFF_H + 8 * hh * PADK + q * 128;
    float*       HTw = sm + OFF_H + 8 * hh * PADK + q * 128;
    const float* WpA = sm + OFF_WA + q * 128;
    const float* WpB = sm + OFF_WB + q * 128;
    float* redA = sm + OFF_RED + q * (16 * APAD);
    float* redB = sm + OFF_RED + q * (16 * BPAD);

    for (int t = 0; t < Tlen; t++) {
        const unsigned par = (unsigned)(t & 1);

        // ============ Phase A: h @ [rk0 | rk1] ============
        float4 pv = make_float4(0.f, 0.f, 0.f, 0.f);
        if (isA0)
            pv = __ldcg((const float4*)(g_P0 + ((size_t)t * Bsz + r0 + frow) * Udim
                                        + cbaseA + fcA));

        load_strip(HTw, g_h + (size_t)(r0 + 8 * hh) * Udim + 128 * q);

        u64 acc[2][8];
#pragma unroll
        for (int i = 0; i < 2; i++)
#pragma unroll
            for (int jj = 0; jj < 8; jj++) acc[i][jj] = 0ull;

#pragma unroll 2
        for (int kc = 0; kc < 32; kc++) {
            const int k = kc * 4;
            ulonglong2 Wv[8];
#pragma unroll
            for (int jj = 0; jj < 8; jj++)
                Wv[jj] = *(const ulonglong2*)(WpA + (cg + 8 * jj) * PADK + k);
#pragma unroll
            for (int i = 0; i < 2; i++) {
                ulonglong2 Hv = *(const ulonglong2*)(Hp + (rg + 4 * i) * PADK + k);
#pragma unroll
                for (int jj = 0; jj < 8; jj++) {
                    acc[i][jj] = ffma2(Hv.x, Wv[jj].x, acc[i][jj]);
                    acc[i][jj] = ffma2(Hv.y, Wv[jj].y, acc[i][jj]);
                }
            }
        }
        __syncthreads();   // H reads done before RED overwrite

#pragma unroll
        for (int i = 0; i < 2; i++)
#pragma unroll
            for (int jj = 0; jj < 8; jj++)
                redA[(8 * hh + rg + 4 * i) * APAD + cg + 8 * jj] = fsum(acc[i][jj]);
        __syncthreads();

        {
            float4 s = make_float4(0.f, 0.f, 0.f, 0.f);
#pragma unroll
            for (int p = 0; p < 4; p++) {
                float4 v = *(const float4*)(sm + OFF_RED + p * (16 * APAD)
                                            + frow * APAD + fcA);
                s.x += v.x; s.y += v.y; s.z += v.z; s.w += v.w;
            }
            int grow = (r0 + frow) * Udim + cbaseA + fcA;
            if (isA0) {
                float4 o;
                o.x = tanh_fast(s.x + pv.x);
                o.y = tanh_fast(s.y + pv.y);
                o.z = tanh_fast(s.z + pv.z);
                o.w = tanh_fast(s.w + pv.w);
                *(float4*)(g_h0 + grow) = o;
            } else {
                *(float4*)(g_r1 + grow) = make_float4(s.x + b1v.x, s.y + b1v.y,
                                                      s.z + b1v.z, s.w + b1v.w);
            }
        }
        __syncthreads();                          // finalize STGs ordered
        if (tid < GSZ) mbar_arrive_rank(mbarA, (unsigned)tid);
        mbar_wait(mbarA, par);                    // warps exit independently

        // ============ Phase B: h0 @ k1 ============
        float2 r1v = __ldcg((const float2*)(g_r1 + (size_t)(r0 + frow) * Udim
                                            + cbaseB + fcB));

        load_strip(HTw, g_h0 + (size_t)(r0 + 8 * hh) * Udim + 128 * q);

        u64 acc2[2][4];
#pragma unroll
        for (int i = 0; i < 2; i++)
#pragma unroll
            for (int jj = 0; jj < 4; jj++) acc2[i][jj] = 0ull;

#pragma unroll 2
        for (int kc = 0; kc < 32; kc++) {
            const int k = kc * 4;
            ulonglong2 Wv[4];
#pragma unroll
            for (int jj = 0; jj < 4; jj++)
                Wv[jj] = *(const ulonglong2*)(WpB + (cg + 8 * jj) * PADK + k);
#pragma unroll
            for (int i = 0; i < 2; i++) {
                ulonglong2 Hv = *(const ulonglong2*)(Hp + (rg + 4 * i) * PADK + k);
#pragma unroll
                for (int jj = 0; jj < 4; jj++) {
                    acc2[i][jj] = ffma2(Hv.x, Wv[jj].x, acc2[i][jj]);
                    acc2[i][jj] = ffma2(Hv.y, Wv[jj].y, acc2[i][jj]);
                }
            }
        }
        __syncthreads();

#pragma unroll
        for (int i = 0; i < 2; i++)
#pragma unroll
            for (int jj = 0; jj < 4; jj++)
                redB[(8 * hh + rg + 4 * i) * BPAD + cg + 8 * jj] = fsum(acc2[i][jj]);
        __syncthreads();

        {
            float2 s = make_float2(0.f, 0.f);
#pragma unroll
            for (int p = 0; p < 4; p++) {
                float2 v = *(const float2*)(sm + OFF_RED + p * (16 * BPAD)
                                            + frow * BPAD + fcB);
                s.x += v.x; s.y += v.y;
            }
            int grow = (r0 + frow) * Udim + cbaseB + fcB;
            float2 o;
            o.x = tanh_fast(s.x + r1v.x);
            o.y = tanh_fast(s.y + r1v.y);
            *(float2*)(g_h + grow) = o;
        }
        __syncthreads();
        if (tid < GSZ) mbar_arrive_rank(mbarB, (unsigned)tid);
        mbar_wait(mbarB, par);
    }

    // ---- output head: sigmoid(h @ wd + bd), rank 0 of each cluster ----
    if (j == 0) {
        int row = r0 + (tid >> 4);
        int p   = tid & 15;
        const float4* hv = (const float4*)(g_h + row * Udim + p * 32);
        const float4* wv = (const float4*)(wd + p * 32);
        float s = 0.f;
#pragma unroll
        for (int qq = 0; qq < 8; qq++) {
            float4 a = __ldcg(hv + qq);
            float4 b = wv[qq];
            s += a.x * b.x + a.y * b.y + a.z * b.z + a.w * b.w;
        }
        s += __shfl_xor_sync(0xffffffffu, s, 1);
        s += __shfl_xor_sync(0xffffffffu, s, 2);
        s += __shfl_xor_sync(0xffffffffu, s, 4);
        s += __shfl_xor_sync(0xffffffffu, s, 8);
        if (p == 0) out[row] = 1.0f / (1.0f + __expf(-(s + bd[0])));
    }
    cluster_sync();   // no CTA exits while peers may still arrive on it
}

// ---------------- launch ----------------

extern "C" void kernel_launch(void* const* d_in, const int* in_sizes, int n_in,
                              void* d_out, int out_size) {
    const int*   tokens = (const int*)  d_in[0];
    const float* emb    = (const float*)d_in[1];
    const float* k0     = (const float*)d_in[2];
    const float* rk0    = (const float*)d_in[3];
    const float* b0     = (const float*)d_in[4];
    const float* k1     = (const float*)d_in[5];
    const float* rk1    = (const float*)d_in[6];
    const float* b1     = (const float*)d_in[7];
    const float* wd     = (const float*)d_in[8];
    const float* bd     = (const float*)d_in[9];
    float* out = (float*)d_out;

    (void)in_sizes; (void)n_in; (void)out_size;

    cudaFuncSetAttribute(rnn_kernel, cudaFuncAttributeMaxDynamicSharedMemorySize, SMEM_BYTES);
    cudaFuncSetAttribute(rnn_kernel, cudaFuncAttributeNonPortableClusterSizeAllowed, 1);

    pre_kernel<<<(Bsz * Tlen) / PC_PAIRS, PTHR>>>(tokens, emb, k0, b0);
    rnn_kernel<<<NCTA, NTHR, SMEM_BYTES>>>(rk0, rk1, k1, b1, wd, bd, out);
}

// round 17
// speedup vs baseline: 1.7620x; 1.7620x over previous
#include <cuda_runtime.h>
#include <cuda_bf16.h>

#define Bsz   128
#define Tlen  80
#define Edim  100
#define Udim  512

// 8 row-groups (16 rows) x 16 col-slice CTAs, 8 warps/CTA.
// Warp (q=w&3, hh=w>>2): K-slice [128q,128q+128), rows [8hh,8hh+8).
#define NCTA  128
#define NTHR  256
#define GSZ   16
#define NGRP  8
#define RPC   16
#define PADK  516
#define APAD  72
#define BPAD  40

#define OFF_WA 0                          // 64 cols x PADK
#define OFF_WB (64 * PADK)                // 32 cols x PADK
#define OFF_H  (96 * PADK)                // 16 rows x PADK (strip area)
#define OFF_RED OFF_H                     // RED overlaps H (H dead post-FMA)
#define OFF_FLAG (OFF_H + RPC * PADK)     // 1 word + pad
#define SMEM_FLOATS (OFF_FLAG + 32)
#define SMEM_BYTES  (SMEM_FLOATS * 4)     // 231296 B <= 232448

typedef unsigned long long u64;

__device__ float g_P0[Tlen * Bsz * Udim];
__device__ float g_h [Bsz * Udim];
__device__ float g_h0[Bsz * Udim];
__device__ float g_r1[Bsz * Udim];
__device__ unsigned g_ctr[NGRP * 32];

// ---------------- helpers ----------------

__device__ __forceinline__ u64 ffma2(u64 a, u64 b, u64 c) {
    u64 d;
    asm("fma.rn.f32x2 %0, %1, %2, %3;" : "=l"(d) : "l"(a), "l"(b), "l"(c));
    return d;
}
__device__ __forceinline__ float fsum(u64 v) {
    float lo, hi;
    asm("mov.b64 {%0, %1}, %2;" : "=f"(lo), "=f"(hi) : "l"(v));
    return lo + hi;
}
__device__ __forceinline__ float tanh_fast(float x) {
    float e = __expf(2.0f * x);
    return 1.0f - __fdividef(2.0f, e + 1.0f);
}
__device__ __forceinline__ void st_rel_cta(unsigned* p, unsigned v) {
    asm volatile("st.release.cta.u32 [%0], %1;" :: "l"(p), "r"(v) : "memory");
}
__device__ __forceinline__ unsigned ld_acq_cta(const unsigned* p) {
    unsigned v;
    asm volatile("ld.acquire.cta.u32 %0, [%1];" : "=r"(v) : "l"(p) : "memory");
    return v;
}

// Barrier with warp-independent release (R15-proven). Leading __syncthreads
// orders all local stores (and finalize reads of RED) before arrive / strip
// overwrite. tid0 is the single global poller (L2-safe); publishes via a
// local SMEM flag; warps exit independently.
__device__ __forceinline__ void gwait(unsigned* ctr, unsigned target,
                                      unsigned* flag, unsigned phase) {
    __syncthreads();
    if (threadIdx.x == 0) {
        asm volatile("red.release.gpu.global.add.u32 [%0], %1;"
                     :: "l"(ctr), "r"(1u) : "memory");
        unsigned v;
        do {
            asm volatile("ld.acquire.gpu.global.u32 %0, [%1];"
                         : "=r"(v) : "l"(ctr) : "memory");
        } while (v < target);
        st_rel_cta(flag, phase);
    }
    while (ld_acq_cta(flag) < phase) { }
}

// Warp loads its own 8-row x 128-col window (coalesced LDG.128, clean STS).
__device__ __forceinline__ void load_strip(float* HTw, const float* src) {
    const int lane = threadIdx.x & 31;
    float4 v[8];
#pragma unroll
    for (int r = 0; r < 8; r++)
        v[r] = __ldcg((const float4*)(src + r * Udim) + lane);
#pragma unroll
    for (int r = 0; r < 8; r++)
        *(float4*)(HTw + r * PADK + lane * 4) = v[r];
    __syncwarp();
}

// ---------------- kernel 1: P0 = emb[tokens] @ k0 + b0 ----------------

#define PC_PAIRS 16
#define PTHR 128

__global__ void __launch_bounds__(PTHR) pre_kernel(
    const int* __restrict__ tokens, const float* __restrict__ emb,
    const float* __restrict__ k0, const float* __restrict__ b0)
{
    __shared__ int    tok[PC_PAIRS];
    __shared__ float2 xs2[PC_PAIRS][Edim];

    const int tid = threadIdx.x;

    if (blockIdx.x == 0 && tid < NGRP) g_ctr[tid * 32] = 0u;

    if (blockIdx.x < 64) {
        int base = blockIdx.x * 1024 + tid * 8;
        float4 z = make_float4(0.f, 0.f, 0.f, 0.f);
        *(float4*)(g_h + base)     = z;
        *(float4*)(g_h + base + 4) = z;
    }

    const int pbase = blockIdx.x * PC_PAIRS;
    if (tid < PC_PAIRS) tok[tid] = tokens[pbase + tid];
    __syncthreads();

    for (int e = tid; e < PC_PAIRS * Edim; e += PTHR) {
        int p = e / Edim, k = e - p * Edim;
        float v = emb[tok[p] * Edim + k];
        xs2[p][k] = make_float2(v, v);
    }
    __syncthreads();

    const int u = tid * 4;
    u64 acc[PC_PAIRS][2];
#pragma unroll
    for (int p = 0; p < PC_PAIRS; p++) { acc[p][0] = 0ull; acc[p][1] = 0ull; }

    for (int k = 0; k < Edim; k++) {
        ulonglong2 wv = *(const ulonglong2*)(k0 + k * Udim + u);
#pragma unroll
        for (int p = 0; p < PC_PAIRS; p++) {
            u64 x2 = *(const u64*)&xs2[p][k];
            acc[p][0] = ffma2(x2, wv.x, acc[p][0]);
            acc[p][1] = ffma2(x2, wv.y, acc[p][1]);
        }
    }

    float4 bv = *(const float4*)(b0 + u);
#pragma unroll
    for (int p = 0; p < PC_PAIRS; p++) {
        int pi = pbase + p;
        int b = pi / Tlen;
        int t = pi - b * Tlen;
        float2 lo, hi;
        asm("mov.b64 {%0, %1}, %2;" : "=f"(lo.x), "=f"(lo.y) : "l"(acc[p][0]));
        asm("mov.b64 {%0, %1}, %2;" : "=f"(hi.x), "=f"(hi.y) : "l"(acc[p][1]));
        float4 o = make_float4(lo.x + bv.x, lo.y + bv.y, hi.x + bv.z, hi.y + bv.w);
        *(float4*)(g_P0 + ((size_t)(t * Bsz) + b) * Udim + u) = o;
    }
}

// ---------------- kernel 2: persistent scan ----------------

__global__ void __launch_bounds__(NTHR, 1) rnn_kernel(
    const float* __restrict__ rk0, const float* __restrict__ rk1,
    const float* __restrict__ k1,  const float* __restrict__ b1,
    const float* __restrict__ wd,  const float* __restrict__ bd,
    float* __restrict__ out)
{
    extern __shared__ float sm[];
    const int tid  = threadIdx.x;
    const int g    = blockIdx.x >> 4;
    const int j    = blockIdx.x & 15;
    const int r0   = g * RPC;
    const int w    = tid >> 5;
    const int lane = tid & 31;
    const int q    = w & 3;
    const int hh   = w >> 2;
    const bool isA0 = (j < 8);

    unsigned* ctr  = g_ctr + g * 32;
    unsigned* flag = (unsigned*)(sm + OFF_FLAG);

    // weights into SMEM (once), transposed [col][K]
    const float* wsrcA = isA0 ? rk0 : rk1;
    const int cbaseA = (j & 7) * 64;
    for (int e = tid; e < 64 * Udim; e += NTHR) {
        int k = e >> 6, cc = e & 63;
        sm[OFF_WA + cc * PADK + k] = wsrcA[k * Udim + cbaseA + cc];
    }
    const int cbaseB = j * 32;
    for (int e = tid; e < 32 * Udim; e += NTHR) {
        int k = e >> 5, cc = e & 31;
        sm[OFF_WB + cc * PADK + k] = k1[k * Udim + cbaseB + cc];
    }

    const int rg = lane & 3;
    const int cg = lane >> 2;

    const int frow = tid >> 4;            // 0..15
    const int fcA  = (tid & 15) * 4;
    const int fcB  = (tid & 15) * 2;

    float4 b1v = make_float4(0.f, 0.f, 0.f, 0.f);
    if (!isA0) b1v = *(const float4*)(b1 + cbaseA + fcA);
    if (tid == 0) *flag = 0u;
    __syncthreads();

    const float* Hp  = sm + OFF_H + 8 * hh * PADK + q * 128;
    float*       HTw = sm + OFF_H + 8 * hh * PADK + q * 128;
    const float* WpA = sm + OFF_WA + q * 128;
    const float* WpB = sm + OFF_WB + q * 128;
    float* redA = sm + OFF_RED + q * (16 * APAD);
    float* redB = sm + OFF_RED + q * (16 * BPAD);

    for (int t = 0; t < Tlen; t++) {
        // ============ Phase A: h @ [rk0 | rk1] ============
        float4 pv = make_float4(0.f, 0.f, 0.f, 0.f);
        if (isA0)
            pv = __ldcg((const float4*)(g_P0 + ((size_t)t * Bsz + r0 + frow) * Udim
                                        + cbaseA + fcA));

        load_strip(HTw, g_h + (size_t)(r0 + 8 * hh) * Udim + 128 * q);

        u64 acc[2][8];
#pragma unroll
        for (int i = 0; i < 2; i++)
#pragma unroll
            for (int jj = 0; jj < 8; jj++) acc[i][jj] = 0ull;

#pragma unroll 4
        for (int kc = 0; kc < 32; kc++) {
            const int k = kc * 4;
            ulonglong2 Wv[8];
#pragma unroll
            for (int jj = 0; jj < 8; jj++)
                Wv[jj] = *(const ulonglong2*)(WpA + (cg + 8 * jj) * PADK + k);
#pragma unroll
            for (int i = 0; i < 2; i++) {
                ulonglong2 Hv = *(const ulonglong2*)(Hp + (rg + 4 * i) * PADK + k);
#pragma unroll
                for (int jj = 0; jj < 8; jj++) {
                    acc[i][jj] = ffma2(Hv.x, Wv[jj].x, acc[i][jj]);
                    acc[i][jj] = ffma2(Hv.y, Wv[jj].y, acc[i][jj]);
                }
            }
        }
        __syncthreads();   // H reads done before RED overwrite

#pragma unroll
        for (int i = 0; i < 2; i++)
#pragma unroll
            for (int jj = 0; jj < 8; jj++)
                redA[(8 * hh + rg + 4 * i) * APAD + cg + 8 * jj] = fsum(acc[i][jj]);
        __syncthreads();

        {
            float4 s = make_float4(0.f, 0.f, 0.f, 0.f);
#pragma unroll
            for (int p = 0; p < 4; p++) {
                float4 v = *(const float4*)(sm + OFF_RED + p * (16 * APAD)
                                            + frow * APAD + fcA);
                s.x += v.x; s.y += v.y; s.z += v.z; s.w += v.w;
            }
            int grow = (r0 + frow) * Udim + cbaseA + fcA;
            if (isA0) {
                float4 o;
                o.x = tanh_fast(s.x + pv.x);
                o.y = tanh_fast(s.y + pv.y);
                o.z = tanh_fast(s.z + pv.z);
                o.w = tanh_fast(s.w + pv.w);
                *(float4*)(g_h0 + grow) = o;
            } else {
                *(float4*)(g_r1 + grow) = make_float4(s.x + b1v.x, s.y + b1v.y,
                                                      s.z + b1v.z, s.w + b1v.w);
            }
        }
        gwait(ctr, (unsigned)(GSZ * (2 * t + 1)), flag, (unsigned)(2 * t + 1));

        // ============ Phase B: h0 @ k1 ============
        float2 r1v = __ldcg((const float2*)(g_r1 + (size_t)(r0 + frow) * Udim
                                            + cbaseB + fcB));

        load_strip(HTw, g_h0 + (size_t)(r0 + 8 * hh) * Udim + 128 * q);

        u64 acc2[2][4];
#pragma unroll
        for (int i = 0; i < 2; i++)
#pragma unroll
            for (int jj = 0; jj < 4; jj++) acc2[i][jj] = 0ull;

#pragma unroll 4
        for (int kc = 0; kc < 32; kc++) {
            const int k = kc * 4;
            ulonglong2 Wv[4];
#pragma unroll
            for (int jj = 0; jj < 4; jj++)
                Wv[jj] = *(const ulonglong2*)(WpB + (cg + 8 * jj) * PADK + k);
#pragma unroll
            for (int i = 0; i < 2; i++) {
                ulonglong2 Hv = *(const ulonglong2*)(Hp + (rg + 4 * i) * PADK + k);
#pragma unroll
                for (int jj = 0; jj < 4; jj++) {
                    acc2[i][jj] = ffma2(Hv.x, Wv[jj].x, acc2[i][jj]);
                    acc2[i][jj] = ffma2(Hv.y, Wv[jj].y, acc2[i][jj]);
                }
            }
        }
        __syncthreads();

#pragma unroll
        for (int i = 0; i < 2; i++)
#pragma unroll
            for (int jj = 0; jj < 4; jj++)
                redB[(8 * hh + rg + 4 * i) * BPAD + cg + 8 * jj] = fsum(acc2[i][jj]);
        __syncthreads();

        {
            float2 s = make_float2(0.f, 0.f);
#pragma unroll
            for (int p = 0; p < 4; p++) {
                float2 v = *(const float2*)(sm + OFF_RED + p * (16 * BPAD)
                                            + frow * BPAD + fcB);
                s.x += v.x; s.y += v.y;
            }
            int grow = (r0 + frow) * Udim + cbaseB + fcB;
            float2 o;
            o.x = tanh_fast(s.x + r1v.x);
            o.y = tanh_fast(s.y + r1v.y);
            *(float2*)(g_h + grow) = o;
        }
        gwait(ctr, (unsigned)(GSZ * (2 * t + 2)), flag, (unsigned)(2 * t + 2));
    }

    // ---- output head: sigmoid(h @ wd + bd), CTA j==0 of each group ----
    if (j == 0) {
        int row = r0 + (tid >> 4);
        int p   = tid & 15;
        const float4* hv = (const float4*)(g_h + row * Udim + p * 32);
        const float4* wv = (const float4*)(wd + p * 32);
        float s = 0.f;
#pragma unroll
        for (int qq = 0; qq < 8; qq++) {
            float4 a = __ldcg(hv + qq);
            float4 b = wv[qq];
            s += a.x * b.x + a.y * b.y + a.z * b.z + a.w * b.w;
        }
        s += __shfl_xor_sync(0xffffffffu, s, 1);
        s += __shfl_xor_sync(0xffffffffu, s, 2);
        s += __shfl_xor_sync(0xffffffffu, s, 4);
        s += __shfl_xor_sync(0xffffffffu, s, 8);
        if (p == 0) out[row] = 1.0f / (1.0f + __expf(-(s + bd[0])));
    }
}

// ---------------- launch ----------------

extern "C" void kernel_launch(void* const* d_in, const int* in_sizes, int n_in,
                              void* d_out, int out_size) {
    const int*   tokens = (const int*)  d_in[0];
    const float* emb    = (const float*)d_in[1];
    const float* k0     = (const float*)d_in[2];
    const float* rk0    = (const float*)d_in[3];
    const float* b0     = (const float*)d_in[4];
    const float* k1     = (const float*)d_in[5];
    const float* rk1    = (const float*)d_in[6];
    const float* b1     = (const float*)d_in[7];
    const float* wd     = (const float*)d_in[8];
    const float* bd     = (const float*)d_in[9];
    float* out = (float*)d_out;

    (void)in_sizes; (void)n_in; (void)out_size;

    cudaFuncSetAttribute(rnn_kernel, cudaFuncAttributeMaxDynamicSharedMemorySize, SMEM_BYTES);

    pre_kernel<<<(Bsz * Tlen) / PC_PAIRS, PTHR>>>(tokens, emb, k0, b0);
    rnn_kernel<<<NCTA, NTHR, SMEM_BYTES>>>(rk0, rk1, k1, b1, wd, bd, out);
}